// round 2
// baseline (speedup 1.0000x reference)
#include <cuda_runtime.h>
#include <cstdint>

#define N_NODES  100000
#define N_GRAPHS 512
#define D        128
#define N_LAYERS 4
#define LN_EPS   1e-5f

// ---------------- scratch (device globals; no allocation allowed) ----------------
__device__ float g_h  [(size_t)N_NODES * D];   // h = x @ W
__device__ float g_agg[(size_t)N_NODES * D];   // aggregation buffer
__device__ float g_cur[(size_t)N_NODES * D];   // current layer activations (ping)
__device__ float g_dis[N_NODES];               // deg^-1/2
__device__ int   g_deg[N_NODES];
__device__ float g_pool[N_GRAPHS * D];
__device__ float g_cnt [N_GRAPHS];

// ---------------- helpers ----------------
__device__ __forceinline__ void red_add_v4(float* p, float a, float b, float c, float d) {
    asm volatile("red.global.add.v4.f32 [%0], {%1,%2,%3,%4};"
                 :: "l"(p), "f"(a), "f"(b), "f"(c), "f"(d) : "memory");
}

// ---------------- kernels ----------------
__global__ void zero_kernel() {
    int i = blockIdx.x * blockDim.x + threadIdx.x;
    int stride = gridDim.x * blockDim.x;
    for (int j = i; j < N_NODES; j += stride) g_deg[j] = 0;
    for (int j = i; j < N_GRAPHS * D; j += stride) g_pool[j] = 0.f;
    for (int j = i; j < N_GRAPHS; j += stride) g_cnt[j] = 0.f;
}

__global__ void deg_kernel(const int* __restrict__ dst, int E) {
    int i = blockIdx.x * blockDim.x + threadIdx.x;
    if (i < E) atomicAdd(&g_deg[dst[i]], 1);
}

__global__ void dis_kernel(int n) {
    int i = blockIdx.x * blockDim.x + threadIdx.x;
    if (i < n) g_dis[i] = rsqrtf((float)g_deg[i] + 1.0f);
}

// H = X @ W   (X: [n,128], W: [128,128] row-major)
// Also seeds AGG = H * dis^2 (self-loop term) so no memset of AGG is needed.
// Block: 256 threads, 64 rows x 128 cols per block. Thread: 8 rows x 4 cols.
__global__ __launch_bounds__(256) void gemm_kernel(const float* __restrict__ Xext,
                                                   const float* __restrict__ W,
                                                   int useCur, int n) {
    __shared__ float Ws[8][128];
    __shared__ float Xs[64][8];

    const float* X = useCur ? g_cur : Xext;

    int tx   = threadIdx.x;
    int lane = tx & 31;
    int wrp  = tx >> 5;
    int c    = lane * 4;          // output column group
    int r0   = wrp * 8;           // row group within tile
    int row0 = blockIdx.x * 64;

    float acc[8][4];
    #pragma unroll
    for (int i = 0; i < 8; i++)
        #pragma unroll
        for (int j = 0; j < 4; j++) acc[i][j] = 0.f;

    for (int k0 = 0; k0 < 128; k0 += 8) {
        // load W tile: 8x128 floats, 4 per thread (float4)
        {
            int linear = tx * 4;
            int kk = linear >> 7;
            int cc = linear & 127;
            float4 w = *(const float4*)(W + (size_t)(k0 + kk) * 128 + cc);
            *(float4*)(&Ws[kk][cc]) = w;
        }
        // load X tile: 64x8 floats, 2 per thread (float2)
        {
            int linear = tx * 2;
            int r  = linear >> 3;
            int kk = linear & 7;
            int row = row0 + r;
            float2 xv = make_float2(0.f, 0.f);
            if (row < n) xv = *(const float2*)(X + (size_t)row * 128 + k0 + kk);
            Xs[r][kk]     = xv.x;
            Xs[r][kk + 1] = xv.y;
        }
        __syncthreads();
        #pragma unroll
        for (int kk = 0; kk < 8; kk++) {
            float4 b = *(float4*)(&Ws[kk][c]);
            #pragma unroll
            for (int i = 0; i < 8; i++) {
                float a = Xs[r0 + i][kk];
                acc[i][0] = fmaf(a, b.x, acc[i][0]);
                acc[i][1] = fmaf(a, b.y, acc[i][1]);
                acc[i][2] = fmaf(a, b.z, acc[i][2]);
                acc[i][3] = fmaf(a, b.w, acc[i][3]);
            }
        }
        __syncthreads();
    }

    #pragma unroll
    for (int i = 0; i < 8; i++) {
        int row = row0 + r0 + i;
        if (row < n) {
            float dv = g_dis[row];
            float d2 = dv * dv;
            float4 hv = make_float4(acc[i][0], acc[i][1], acc[i][2], acc[i][3]);
            *(float4*)(g_h   + (size_t)row * 128 + c) = hv;
            float4 av = make_float4(hv.x * d2, hv.y * d2, hv.z * d2, hv.w * d2);
            *(float4*)(g_agg + (size_t)row * 128 + c) = av;
        }
    }
}

// Edge aggregation: one warp per edge, vector RED into agg[dst].
__global__ __launch_bounds__(256) void edge_kernel(const int* __restrict__ src,
                                                   const int* __restrict__ dst,
                                                   int E) {
    int warp = (blockIdx.x * blockDim.x + threadIdx.x) >> 5;
    int lane = threadIdx.x & 31;
    if (warp >= E) return;
    int s = __ldg(&src[warp]);
    int d = __ldg(&dst[warp]);
    float coef = g_dis[s] * g_dis[d];
    float4 v = *(const float4*)(g_h + (size_t)s * 128 + lane * 4);
    float* p = g_agg + (size_t)d * 128 + lane * 4;
    red_add_v4(p, v.x * coef, v.y * coef, v.z * coef, v.w * coef);
}

// LayerNorm(agg + bias) [* residual / relu per layer], warp per node -> g_cur
__global__ __launch_bounds__(256) void ln_kernel(const float* __restrict__ b,
                                                 const float* __restrict__ gamma,
                                                 const float* __restrict__ beta,
                                                 int n, int doRes, int doRelu) {
    int node = (blockIdx.x * blockDim.x + threadIdx.x) >> 5;
    int lane = threadIdx.x & 31;
    if (node >= n) return;

    float4 v  = ((const float4*)(g_agg + (size_t)node * 128))[lane];
    float4 bb = ((const float4*)b)[lane];
    v.x += bb.x; v.y += bb.y; v.z += bb.z; v.w += bb.w;

    float s  = v.x + v.y + v.z + v.w;
    float sq = v.x * v.x + v.y * v.y + v.z * v.z + v.w * v.w;
    #pragma unroll
    for (int o = 16; o > 0; o >>= 1) {
        s  += __shfl_xor_sync(0xffffffffu, s,  o);
        sq += __shfl_xor_sync(0xffffffffu, sq, o);
    }
    float mu  = s * (1.0f / 128.0f);
    float var = sq * (1.0f / 128.0f) - mu * mu;
    float inv = rsqrtf(var + LN_EPS);

    float4 g  = ((const float4*)gamma)[lane];
    float4 be = ((const float4*)beta)[lane];
    float4 o4;
    o4.x = (v.x - mu) * inv * g.x + be.x;
    o4.y = (v.y - mu) * inv * g.y + be.y;
    o4.z = (v.z - mu) * inv * g.z + be.z;
    o4.w = (v.w - mu) * inv * g.w + be.w;

    if (doRes) {
        float4 r = ((const float4*)(g_cur + (size_t)node * 128))[lane];
        o4.x += r.x; o4.y += r.y; o4.z += r.z; o4.w += r.w;
    }
    if (doRelu) {
        o4.x = fmaxf(o4.x, 0.f); o4.y = fmaxf(o4.y, 0.f);
        o4.z = fmaxf(o4.z, 0.f); o4.w = fmaxf(o4.w, 0.f);
    }
    ((float4*)(g_cur + (size_t)node * 128))[lane] = o4;
}

// mean-pool accumulation: warp per node
__global__ __launch_bounds__(256) void pool_kernel(const int* __restrict__ batch, int n) {
    int node = (blockIdx.x * blockDim.x + threadIdx.x) >> 5;
    int lane = threadIdx.x & 31;
    if (node >= n) return;
    int gidx = __ldg(&batch[node]);
    float4 v = ((const float4*)(g_cur + (size_t)node * 128))[lane];
    float* p = g_pool + (size_t)gidx * 128 + lane * 4;
    red_add_v4(p, v.x, v.y, v.z, v.w);
    if (lane == 0) atomicAdd(&g_cnt[gidx], 1.0f);
}

// final linear: warp per graph
__global__ __launch_bounds__(256) void final_kernel(const float* __restrict__ lw,
                                                    const float* __restrict__ lb,
                                                    float* __restrict__ out, int G) {
    int gidx = (blockIdx.x * blockDim.x + threadIdx.x) >> 5;
    int lane = threadIdx.x & 31;
    if (gidx >= G) return;
    float c = fmaxf(g_cnt[gidx], 1.0f);
    float4 p = ((const float4*)(g_pool + (size_t)gidx * 128))[lane];
    float4 w = ((const float4*)lw)[lane];
    float s = (p.x * w.x + p.y * w.y + p.z * w.z + p.w * w.w) / c;
    #pragma unroll
    for (int o = 16; o > 0; o >>= 1) s += __shfl_xor_sync(0xffffffffu, s, o);
    if (lane == 0) out[gidx] = s + lb[0];
}

// ---------------- launch ----------------
extern "C" void kernel_launch(void* const* d_in, const int* in_sizes, int n_in,
                              void* d_out, int out_size) {
    const float* x     = (const float*)d_in[0];
    const int*   eidx  = (const int*)  d_in[1];   // [2, E] int32
    const int*   batch = (const int*)  d_in[2];
    const float* Ws    = (const float*)d_in[3];   // [4,128,128]
    const float* bs    = (const float*)d_in[4];   // [4,128]
    const float* gms   = (const float*)d_in[5];
    const float* bts   = (const float*)d_in[6];
    const float* lw    = (const float*)d_in[7];   // [128,1]
    const float* lb    = (const float*)d_in[8];
    float* out = (float*)d_out;

    int n = in_sizes[0] / D;
    int E = in_sizes[1] / 2;
    int G = out_size;

    const int* src = eidx;
    const int* dst = eidx + E;

    // degree / dis
    zero_kernel<<<512, 256>>>();
    deg_kernel<<<(E + 255) / 256, 256>>>(dst, E);
    dis_kernel<<<(n + 255) / 256, 256>>>(n);

    int gemmBlocks = (n + 63) / 64;
    int warpBlocks = (n + 7) / 8;       // warp-per-node kernels (8 warps / 256-thread block)
    int edgeBlocks = (E + 7) / 8;       // warp-per-edge

    for (int L = 0; L < N_LAYERS; L++) {
        int doRes  = (L > 0) ? 1 : 0;
        int doRelu = (L < N_LAYERS - 1) ? 1 : 0;
        gemm_kernel<<<gemmBlocks, 256>>>(x, Ws + (size_t)L * D * D, (L > 0) ? 1 : 0, n);
        edge_kernel<<<edgeBlocks, 256>>>(src, dst, E);
        ln_kernel<<<warpBlocks, 256>>>(bs + (size_t)L * D, gms + (size_t)L * D,
                                       bts + (size_t)L * D, n, doRes, doRelu);
    }

    pool_kernel<<<warpBlocks, 256>>>(batch, n);
    final_kernel<<<(G + 7) / 8, 256>>>(lw, lb, out, G);
}

// round 3
// speedup vs baseline: 1.7920x; 1.7920x over previous
#include <cuda_runtime.h>
#include <cstdint>

#define N_NODES  100000
#define N_GRAPHS 512
#define D        128
#define N_LAYERS 4
#define LN_EPS   1e-5f
#define MAX_E    1600000
#define SCAN_B   1024

// ---------------- scratch (device globals; no allocation allowed) ----------------
__device__ float g_h  [(size_t)N_NODES * D];   // h = x @ W
__device__ float g_cur[(size_t)N_NODES * D];   // current layer activations
__device__ float g_dis[N_NODES];               // deg^-1/2
__device__ int   g_deg[N_NODES];
__device__ int   g_off[N_NODES];               // exclusive prefix of deg
__device__ int   g_offtmp[N_NODES];
__device__ int   g_pos[N_NODES];               // scatter cursors
__device__ int   g_bsum[(N_NODES + SCAN_B - 1) / SCAN_B];
__device__ int   g_bsumex[(N_NODES + SCAN_B - 1) / SCAN_B];
__device__ int2  g_csr[MAX_E];                 // {src, coef-bits} sorted by dst
__device__ float g_pool[N_GRAPHS * D];
__device__ float g_cnt [N_GRAPHS];

// ---------------- helpers ----------------
__device__ __forceinline__ void red_add_v4(float* p, float a, float b, float c, float d) {
    asm volatile("red.global.add.v4.f32 [%0], {%1,%2,%3,%4};"
                 :: "l"(p), "f"(a), "f"(b), "f"(c), "f"(d) : "memory");
}

// ---------------- setup kernels ----------------
__global__ void zero_kernel() {
    int i = blockIdx.x * blockDim.x + threadIdx.x;
    int stride = gridDim.x * blockDim.x;
    for (int j = i; j < N_NODES; j += stride) { g_deg[j] = 0; g_pos[j] = 0; }
    for (int j = i; j < N_GRAPHS * D; j += stride) g_pool[j] = 0.f;
    for (int j = i; j < N_GRAPHS; j += stride) g_cnt[j] = 0.f;
}

__global__ void deg_kernel(const int* __restrict__ dst, int E) {
    int i = blockIdx.x * blockDim.x + threadIdx.x;
    if (i < E) atomicAdd(&g_deg[dst[i]], 1);
}

// dis = rsqrt(deg+1); also accumulate per-graph node counts
__global__ void dis_kernel(const int* __restrict__ batch, int n) {
    int i = blockIdx.x * blockDim.x + threadIdx.x;
    if (i < n) {
        g_dis[i] = rsqrtf((float)g_deg[i] + 1.0f);
        atomicAdd(&g_cnt[batch[i]], 1.0f);
    }
}

// block-level inclusive scan of deg
__global__ void scan1_kernel(int n) {
    __shared__ int sm[SCAN_B];
    int t = threadIdx.x;
    int i = blockIdx.x * SCAN_B + t;
    int v = (i < n) ? g_deg[i] : 0;
    sm[t] = v;
    __syncthreads();
    #pragma unroll
    for (int o = 1; o < SCAN_B; o <<= 1) {
        int add = (t >= o) ? sm[t - o] : 0;
        __syncthreads();
        sm[t] += add;
        __syncthreads();
    }
    if (i < n) g_offtmp[i] = sm[t];
    if (t == SCAN_B - 1) g_bsum[blockIdx.x] = sm[t];
}

__global__ void scan2_kernel(int nb) {
    if (threadIdx.x == 0) {
        int run = 0;
        for (int b = 0; b < nb; b++) { int s = g_bsum[b]; g_bsumex[b] = run; run += s; }
    }
}

__global__ void scan3_kernel(int n) {
    int i = blockIdx.x * blockDim.x + threadIdx.x;
    if (i < n) g_off[i] = g_offtmp[i] - g_deg[i] + g_bsumex[blockIdx.x * blockDim.x >= 0 ? i / SCAN_B : 0];
}

// scatter edges into CSR sorted by dst, with precomputed coef
__global__ void scatter_kernel(const int* __restrict__ src, const int* __restrict__ dst, int E) {
    int e = blockIdx.x * blockDim.x + threadIdx.x;
    if (e >= E) return;
    int s = src[e];
    int d = dst[e];
    int pos = g_off[d] + atomicAdd(&g_pos[d], 1);
    float coef = g_dis[s] * g_dis[d];
    g_csr[pos] = make_int2(s, __float_as_int(coef));
}

// ---------------- GEMM: H = X @ W ----------------
__global__ __launch_bounds__(256) void gemm_kernel(const float* __restrict__ Xext,
                                                   const float* __restrict__ W,
                                                   int useCur, int n) {
    __shared__ float Ws[8][128];
    __shared__ float Xs[64][8];

    const float* X = useCur ? g_cur : Xext;

    int tx   = threadIdx.x;
    int lane = tx & 31;
    int wrp  = tx >> 5;
    int c    = lane * 4;
    int r0   = wrp * 8;
    int row0 = blockIdx.x * 64;

    float acc[8][4];
    #pragma unroll
    for (int i = 0; i < 8; i++)
        #pragma unroll
        for (int j = 0; j < 4; j++) acc[i][j] = 0.f;

    for (int k0 = 0; k0 < 128; k0 += 8) {
        {
            int linear = tx * 4;
            int kk = linear >> 7;
            int cc = linear & 127;
            float4 w = *(const float4*)(W + (size_t)(k0 + kk) * 128 + cc);
            *(float4*)(&Ws[kk][cc]) = w;
        }
        {
            int linear = tx * 2;
            int r  = linear >> 3;
            int kk = linear & 7;
            int row = row0 + r;
            float2 xv = make_float2(0.f, 0.f);
            if (row < n) xv = *(const float2*)(X + (size_t)row * 128 + k0 + kk);
            Xs[r][kk]     = xv.x;
            Xs[r][kk + 1] = xv.y;
        }
        __syncthreads();
        #pragma unroll
        for (int kk = 0; kk < 8; kk++) {
            float4 b = *(float4*)(&Ws[kk][c]);
            #pragma unroll
            for (int i = 0; i < 8; i++) {
                float a = Xs[r0 + i][kk];
                acc[i][0] = fmaf(a, b.x, acc[i][0]);
                acc[i][1] = fmaf(a, b.y, acc[i][1]);
                acc[i][2] = fmaf(a, b.z, acc[i][2]);
                acc[i][3] = fmaf(a, b.w, acc[i][3]);
            }
        }
        __syncthreads();
    }

    #pragma unroll
    for (int i = 0; i < 8; i++) {
        int row = row0 + r0 + i;
        if (row < n)
            *(float4*)(g_h + (size_t)row * 128 + c) =
                make_float4(acc[i][0], acc[i][1], acc[i][2], acc[i][3]);
    }
}

// ---------------- fused aggregate + bias + LN + residual + relu (+pool) ----------------
// warp per node. acc[lane] covers 4 columns. CSR gather, register accumulation.
__global__ __launch_bounds__(256) void agg_ln_kernel(const float* __restrict__ b,
                                                     const float* __restrict__ gamma,
                                                     const float* __restrict__ beta,
                                                     const int* __restrict__ batch,
                                                     int n, int doRes, int doRelu, int doPool) {
    int node = (blockIdx.x * blockDim.x + threadIdx.x) >> 5;
    int lane = threadIdx.x & 31;
    if (node >= n) return;

    float dv = g_dis[node];
    float d2 = dv * dv;
    float4 hv = ((const float4*)(g_h + (size_t)node * 128))[lane];
    float4 acc = make_float4(hv.x * d2, hv.y * d2, hv.z * d2, hv.w * d2);

    int base = g_off[node];
    int deg  = g_deg[node];
    const int2* ep = g_csr + base;

    int i = 0;
    for (; i + 4 <= deg; i += 4) {
        int2 p0 = ep[i], p1 = ep[i + 1], p2 = ep[i + 2], p3 = ep[i + 3];
        float4 v0 = ((const float4*)(g_h + (size_t)p0.x * 128))[lane];
        float4 v1 = ((const float4*)(g_h + (size_t)p1.x * 128))[lane];
        float4 v2 = ((const float4*)(g_h + (size_t)p2.x * 128))[lane];
        float4 v3 = ((const float4*)(g_h + (size_t)p3.x * 128))[lane];
        float c0 = __int_as_float(p0.y), c1 = __int_as_float(p1.y);
        float c2 = __int_as_float(p2.y), c3 = __int_as_float(p3.y);
        acc.x = fmaf(c0, v0.x, acc.x); acc.y = fmaf(c0, v0.y, acc.y);
        acc.z = fmaf(c0, v0.z, acc.z); acc.w = fmaf(c0, v0.w, acc.w);
        acc.x = fmaf(c1, v1.x, acc.x); acc.y = fmaf(c1, v1.y, acc.y);
        acc.z = fmaf(c1, v1.z, acc.z); acc.w = fmaf(c1, v1.w, acc.w);
        acc.x = fmaf(c2, v2.x, acc.x); acc.y = fmaf(c2, v2.y, acc.y);
        acc.z = fmaf(c2, v2.z, acc.z); acc.w = fmaf(c2, v2.w, acc.w);
        acc.x = fmaf(c3, v3.x, acc.x); acc.y = fmaf(c3, v3.y, acc.y);
        acc.z = fmaf(c3, v3.z, acc.z); acc.w = fmaf(c3, v3.w, acc.w);
    }
    for (; i < deg; i++) {
        int2 p = ep[i];
        float cc = __int_as_float(p.y);
        float4 v = ((const float4*)(g_h + (size_t)p.x * 128))[lane];
        acc.x = fmaf(cc, v.x, acc.x); acc.y = fmaf(cc, v.y, acc.y);
        acc.z = fmaf(cc, v.z, acc.z); acc.w = fmaf(cc, v.w, acc.w);
    }

    // + bias
    float4 bb = ((const float4*)b)[lane];
    acc.x += bb.x; acc.y += bb.y; acc.z += bb.z; acc.w += bb.w;

    // LayerNorm
    float s  = acc.x + acc.y + acc.z + acc.w;
    float sq = acc.x * acc.x + acc.y * acc.y + acc.z * acc.z + acc.w * acc.w;
    #pragma unroll
    for (int o = 16; o > 0; o >>= 1) {
        s  += __shfl_xor_sync(0xffffffffu, s,  o);
        sq += __shfl_xor_sync(0xffffffffu, sq, o);
    }
    float mu  = s * (1.0f / 128.0f);
    float var = sq * (1.0f / 128.0f) - mu * mu;
    float inv = rsqrtf(var + LN_EPS);

    float4 g  = ((const float4*)gamma)[lane];
    float4 be = ((const float4*)beta)[lane];
    float4 o4;
    o4.x = (acc.x - mu) * inv * g.x + be.x;
    o4.y = (acc.y - mu) * inv * g.y + be.y;
    o4.z = (acc.z - mu) * inv * g.z + be.z;
    o4.w = (acc.w - mu) * inv * g.w + be.w;

    if (doRes) {
        float4 r = ((const float4*)(g_cur + (size_t)node * 128))[lane];
        o4.x += r.x; o4.y += r.y; o4.z += r.z; o4.w += r.w;
    }
    if (doRelu) {
        o4.x = fmaxf(o4.x, 0.f); o4.y = fmaxf(o4.y, 0.f);
        o4.z = fmaxf(o4.z, 0.f); o4.w = fmaxf(o4.w, 0.f);
    }

    if (doPool) {
        int gidx = __ldg(&batch[node]);
        red_add_v4(g_pool + (size_t)gidx * 128 + lane * 4, o4.x, o4.y, o4.z, o4.w);
    } else {
        ((float4*)(g_cur + (size_t)node * 128))[lane] = o4;
    }
}

// final linear: warp per graph
__global__ __launch_bounds__(256) void final_kernel(const float* __restrict__ lw,
                                                    const float* __restrict__ lb,
                                                    float* __restrict__ out, int G) {
    int gidx = (blockIdx.x * blockDim.x + threadIdx.x) >> 5;
    int lane = threadIdx.x & 31;
    if (gidx >= G) return;
    float c = fmaxf(g_cnt[gidx], 1.0f);
    float4 p = ((const float4*)(g_pool + (size_t)gidx * 128))[lane];
    float4 w = ((const float4*)lw)[lane];
    float s = (p.x * w.x + p.y * w.y + p.z * w.z + p.w * w.w) / c;
    #pragma unroll
    for (int o = 16; o > 0; o >>= 1) s += __shfl_xor_sync(0xffffffffu, s, o);
    if (lane == 0) out[gidx] = s + lb[0];
}

// ---------------- launch ----------------
extern "C" void kernel_launch(void* const* d_in, const int* in_sizes, int n_in,
                              void* d_out, int out_size) {
    const float* x     = (const float*)d_in[0];
    const int*   eidx  = (const int*)  d_in[1];   // [2, E]
    const int*   batch = (const int*)  d_in[2];
    const float* Ws    = (const float*)d_in[3];
    const float* bs    = (const float*)d_in[4];
    const float* gms   = (const float*)d_in[5];
    const float* bts   = (const float*)d_in[6];
    const float* lw    = (const float*)d_in[7];
    const float* lb    = (const float*)d_in[8];
    float* out = (float*)d_out;

    int n = in_sizes[0] / D;
    int E = in_sizes[1] / 2;
    int G = out_size;

    const int* src = eidx;
    const int* dst = eidx + E;

    int nb = (n + SCAN_B - 1) / SCAN_B;

    zero_kernel<<<512, 256>>>();
    deg_kernel<<<(E + 255) / 256, 256>>>(dst, E);
    dis_kernel<<<(n + 255) / 256, 256>>>(batch, n);
    scan1_kernel<<<nb, SCAN_B>>>(n);
    scan2_kernel<<<1, 32>>>(nb);
    scan3_kernel<<<nb, SCAN_B>>>(n);
    scatter_kernel<<<(E + 255) / 256, 256>>>(src, dst, E);

    int gemmBlocks = (n + 63) / 64;
    int warpBlocks = (n + 7) / 8;

    for (int L = 0; L < N_LAYERS; L++) {
        int doRes  = (L > 0) ? 1 : 0;
        int doRelu = (L < N_LAYERS - 1) ? 1 : 0;
        int doPool = (L == N_LAYERS - 1) ? 1 : 0;
        gemm_kernel<<<gemmBlocks, 256>>>(x, Ws + (size_t)L * D * D, (L > 0) ? 1 : 0, n);
        agg_ln_kernel<<<warpBlocks, 256>>>(bs + (size_t)L * D, gms + (size_t)L * D,
                                           bts + (size_t)L * D, batch, n, doRes, doRelu, doPool);
    }

    final_kernel<<<(G + 7) / 8, 256>>>(lw, lb, out, G);
}